// round 11
// baseline (speedup 1.0000x reference)
#include <cuda_runtime.h>
#include <cuda_bf16.h>
#include <cstdint>
#include <math.h>

#define B_    32
#define C_    64
#define H_    64
#define W_    64
#define K_    128
#define OH    62
#define OW    62
#define NPOS  (B_*OH*OW)             // 123008
#define YSZ   ((size_t)B_*K_*OH*OW)  // 15745024
#define UPDSZ (K_*C_*9)              // 73728
#define AMB_CAP 32768

// ---------------------------------------------------------------------------
// device globals
// ---------------------------------------------------------------------------
__device__ __nv_bfloat16 g_xh[(size_t)B_*C_*H_*W_];
__device__ __nv_bfloat16 g_xl[(size_t)B_*C_*H_*W_];
__device__ float g_xt[(size_t)B_*H_*W_*C_];           // NHWC fp32 copy (exact values)
__device__ __nv_bfloat16 g_wpack[9 * 2*4*128*8*2];    // b-frag packed, 288KB total (L2-resident)
__device__ float g_wnf[K_*576];                       // normalized fp32 weights (R2-bit)
__device__ int g_winners[NPOS];
__device__ unsigned int g_ambcnt;
__device__ unsigned int g_amb[AMB_CAP];               // pos | k1<<17 | k2<<24
__device__ int g_kcnt[K_];
__device__ int g_klist[(size_t)K_*NPOS];

// ---------------------------------------------------------------------------
// helpers
// ---------------------------------------------------------------------------
__device__ __forceinline__ uint32_t smem_to_u32(const void* p) {
    uint32_t a;
    asm("{ .reg .u64 t; cvta.to.shared.u64 t, %1; cvt.u32.u64 %0, t; }" : "=r"(a) : "l"(p));
    return a;
}
__device__ __forceinline__ void ldmx4(uint32_t* r, uint32_t addr) {
    asm volatile("ldmatrix.sync.aligned.m8n8.x4.shared.b16 {%0,%1,%2,%3}, [%4];"
                 : "=r"(r[0]), "=r"(r[1]), "=r"(r[2]), "=r"(r[3]) : "r"(addr));
}
__device__ __forceinline__ void mma16816(float* c, const uint32_t* a, const uint32_t* b) {
    asm volatile("mma.sync.aligned.m16n8k16.row.col.f32.bf16.bf16.f32 "
                 "{%0,%1,%2,%3}, {%4,%5,%6,%7}, {%8,%9}, {%0,%1,%2,%3};"
                 : "+f"(c[0]), "+f"(c[1]), "+f"(c[2]), "+f"(c[3])
                 : "r"(a[0]), "r"(a[1]), "r"(a[2]), "r"(a[3]), "r"(b[0]), "r"(b[1]));
}

// ---------------------------------------------------------------------------
__global__ void prep_x_kernel(const float* __restrict__ x) {
    size_t i = (size_t)blockIdx.x * blockDim.x + threadIdx.x;
    if (i >= (size_t)B_*C_*H_*W_) return;
    float v = x[i];
    __nv_bfloat16 h = __float2bfloat16(v);
    __nv_bfloat16 l = __float2bfloat16(v - __bfloat162float(h));
    g_xh[i] = h;
    g_xl[i] = l;
}

// transpose: x NCHW -> g_xt NHWC (exact copy, different layout)
__global__ void __launch_bounds__(256) transpose_kernel(const float* __restrict__ x) {
    __shared__ float t[64][65];
    const int bh = blockIdx.x;
    const int b  = bh >> 6;
    const int h  = bh & 63;
    const int tid = threadIdx.x;
    for (int idx = tid; idx < 4096; idx += 256) {
        int c = idx >> 6, w = idx & 63;
        t[c][w] = x[(((size_t)(b*64 + c))*64 + h)*64 + w];
    }
    __syncthreads();
    for (int idx = tid; idx < 4096; idx += 256) {
        int w = idx >> 6, c = idx & 63;
        g_xt[(((size_t)(b*64 + h))*64 + w)*64 + c] = t[c][w];
    }
}

// prep_w: R2-bit fp32 normalization + bf16 split + b-frag pack + fp32 copy.
__global__ void prep_w_kernel(const float* __restrict__ w) {
    int n  = threadIdx.x;
    int ij = blockIdx.x;
    float s = 0.f;
    for (int i = 0; i < 576; i++) { float v = w[n*576 + i]; s = fmaf(v, v, s); }
    float nm = sqrtf(s);
    if (nm == 0.f) nm = 1.f;
    float inv = 1.0f / nm;
    for (int c = 0; c < C_; c++) {
        float v = w[n*576 + c*9 + ij] * inv;
        g_wnf[n*576 + c*9 + ij] = v;
        __nv_bfloat16 h = __float2bfloat16(v);
        __nv_bfloat16 l = __float2bfloat16(v - __bfloat162float(h));
        int kc   = c >> 4;
        int cc   = c & 15;
        int widx = ((cc >> 1) & 3) * 2 + (cc >> 3);
        int half = cc & 1;
        size_t base = ((((size_t)ij*2 + 0)*4 + kc)*128 + n)*8 + widx;
        g_wpack[base*2 + half] = h;
        base = ((((size_t)ij*2 + 1)*4 + kc)*128 + n)*8 + widx;
        g_wpack[base*2 + half] = l;
    }
}

__global__ void zero_kernel(float* __restrict__ upd) {
    int i = blockIdx.x * blockDim.x + threadIdx.x;
    if (i < UPDSZ) upd[i] = 0.f;
    if (i < K_) g_kcnt[i] = 0;
    if (i == 0) g_ambcnt = 0;
}

// ---------------------------------------------------------------------------
// conv_mma: HMMA GEMM, sync-free mainloop. B fragments via __ldg from the
// L2-resident g_wpack (no W smem staging, no per-stage barriers).
// smem: bias 1KB | Th 32KB | Tl 32KB ; epilogue D[128][130] overlays at 1KB.
// ---------------------------------------------------------------------------
#define SOFF_BIAS 0
#define SOFF_TH   1024
#define SOFF_TL   33792
#define SOFF_D    1024
#define SMEM_BYTES 68608

__global__ void __launch_bounds__(256) conv_mma_kernel(
    const float* __restrict__ bias, float* __restrict__ y)
{
    extern __shared__ unsigned char smem[];
    const uint32_t sb = smem_to_u32(smem);
    const int tid = threadIdx.x;
    const int l   = tid & 31;
    const int wid = tid >> 5;
    const int wm  = wid >> 2;
    const int wn  = wid & 3;
    const int b   = blockIdx.y;
    const int oh0 = blockIdx.x * 2;

    if (tid < 128) ((float*)(smem + SOFF_BIAS))[tid] = bias[tid];

    for (int idx = tid; idx < C_*4*16; idx += 256) {
        int c    = idx >> 6;
        int row  = (idx >> 4) & 3;
        int col4 = (idx & 15) * 4;
        size_t gi = (((size_t)b*C_ + c)*H_ + (oh0 + row))*W_ + col4;
        const __nv_bfloat16* ph = g_xh + gi;
        const __nv_bfloat16* pl = g_xl + gi;
        #pragma unroll
        for (int q = 0; q < 4; q++) {
            int col = col4 + q;
            int rowIdx = row*64 + col;
            uint32_t off = (uint32_t)(rowIdx*128 + c*2) ^ (uint32_t)((rowIdx & 7) << 4);
            *(__nv_bfloat16*)(smem + SOFF_TH + off) = ph[q];
            *(__nv_bfloat16*)(smem + SOFF_TL + off) = pl[q];
        }
    }
    __syncthreads();   // the only mainloop barrier

    float acc[4][4][4] = {};
    const int lrow_lo = (l & 7) + ((l >> 3) & 1) * 8;
    const uint32_t khalf = (uint32_t)((l >> 4) * 16);
    // per-lane B pointer base: uint2 index = (((term*4+kc)*128+n)*4 + (l&3))
    const int nb = wn*32 + (l >> 2);      // n for nt=0; nt adds 8
    const int lw = l & 3;

    #pragma unroll 1
    for (int s = 0; s < 9; s++) {
        const int i = s / 3, j = s - 3*(s/3);
        const uint2* wq = (const uint2*)g_wpack + (size_t)s*4096;

        uint32_t abase[4], asw[4];
        #pragma unroll
        for (int mt = 0; mt < 4; mt++) {
            int m  = wm*64 + mt*16 + lrow_lo;
            int nr = m >> 6, nc = m & 63;
            int pc = nc + j; if (pc > 63) pc = 63;
            int rowIdx = (nr + i)*64 + pc;
            abase[mt] = sb + SOFF_TH + (uint32_t)(rowIdx*128);
            asw[mt]   = (uint32_t)((rowIdx & 7) << 4);
        }

        #pragma unroll
        for (int kc = 0; kc < 4; kc++) {
            const uint32_t koff = (uint32_t)kc * 32;
            uint32_t ah[4][4], bh[4][2], bl[4][2];
            // issue all B LDGs first (L2 hits; latency hidden by ldmatrix+mma)
            #pragma unroll
            for (int nt = 0; nt < 4; nt++) {
                uint2 v0 = __ldg(wq + (((0*4 + kc)*128 + nb + nt*8)*4 + lw));
                bh[nt][0] = v0.x; bh[nt][1] = v0.y;
                uint2 v1 = __ldg(wq + (((1*4 + kc)*128 + nb + nt*8)*4 + lw));
                bl[nt][0] = v1.x; bl[nt][1] = v1.y;
            }
            #pragma unroll
            for (int mt = 0; mt < 4; mt++)
                ldmx4(ah[mt], abase[mt] + ((khalf + koff) ^ asw[mt]));
            #pragma unroll
            for (int mt = 0; mt < 4; mt++)
                #pragma unroll
                for (int nt = 0; nt < 4; nt++)
                    mma16816(acc[mt][nt], ah[mt], bh[nt]);
            {
                uint32_t al[4][4];
                #pragma unroll
                for (int mt = 0; mt < 4; mt++)
                    ldmx4(al[mt], abase[mt] + 32768 + ((khalf + koff) ^ asw[mt]));
                #pragma unroll
                for (int mt = 0; mt < 4; mt++)
                    #pragma unroll
                    for (int nt = 0; nt < 4; nt++)
                        mma16816(acc[mt][nt], al[mt], bh[nt]);
            }
            #pragma unroll
            for (int mt = 0; mt < 4; mt++)
                #pragma unroll
                for (int nt = 0; nt < 4; nt++)
                    mma16816(acc[mt][nt], ah[mt], bl[nt]);
        }
    }

    // ---- epilogue: frags -> smem D[128][130] (overlays Th/Tl) ----
    __syncthreads();
    float* D = (float*)(smem + SOFF_D);
    {
        const int r  = l >> 2;
        const int cq = (l & 3) * 2;
        #pragma unroll
        for (int mt = 0; mt < 4; mt++)
            #pragma unroll
            for (int nt = 0; nt < 4; nt++) {
                int pos = wm*64 + mt*16 + r;
                int k   = wn*32 + nt*8 + cq;
                *(float2*)&D[pos*130 + k]       = make_float2(acc[mt][nt][0], acc[mt][nt][1]);
                *(float2*)&D[(pos + 8)*130 + k] = make_float2(acc[mt][nt][2], acc[mt][nt][3]);
            }
    }
    __syncthreads();

    // ---- per-thread: bias + top-2 argmax + y store; flag near-ties ----
    {
        const int p2   = tid >> 1;
        const int kh2  = (tid & 1) * 64;
        const int nrow = p2 >> 6, ncol = p2 & 63;
        const int oh = oh0 + nrow, ow = ncol;
        const bool valid = (ncol < OW);
        const float* bs = (const float*)(smem + SOFF_BIAS);
        float v1 = -INFINITY, v2 = -INFINITY;
        int   k1 = 0, k2 = 0;
        float* yb = y + ((size_t)b*K_)*OH*OW + (size_t)oh*OW + ow;
        #pragma unroll 4
        for (int k = kh2; k < kh2 + 64; k += 2) {
            float2 d = *(float2*)&D[p2*130 + k];
            float a0 = d.x + bs[k];
            float a1 = d.y + bs[k+1];
            if (a0 > v1) { v2 = v1; k2 = k1; v1 = a0; k1 = k; }
            else if (a0 > v2) { v2 = a0; k2 = k; }
            if (a1 > v1) { v2 = v1; k2 = k1; v1 = a1; k1 = k + 1; }
            else if (a1 > v2) { v2 = a1; k2 = k + 1; }
            if (valid) {
                yb[(size_t)k*OH*OW]     = a0;
                yb[(size_t)(k+1)*OH*OW] = a1;
            }
        }
        __syncthreads();
        float* rv = (float*)(smem + SOFF_D);
        int*   rk = (int*)(smem + SOFF_D + 4096);
        rv[tid*2] = v1; rv[tid*2+1] = v2;
        rk[tid*2] = k1; rk[tid*2+1] = k2;
        __syncthreads();
        if ((tid & 1) == 0 && valid) {
            float w1 = rv[(tid+1)*2], w2 = rv[(tid+1)*2+1];
            int   j1 = rk[(tid+1)*2], j2 = rk[(tid+1)*2+1];
            float t1, t2; int m1, m2;
            if (w1 > v1) { t1 = w1; m1 = j1; t2 = (v1 > w2) ? v1 : w2; m2 = (v1 > w2) ? k1 : j2; }
            else         { t1 = v1; m1 = k1; t2 = (w1 > v2) ? w1 : v2; m2 = (w1 > v2) ? j1 : k2; }
            int pos = (b*OH + oh)*OW + ow;
            g_winners[pos] = m1;
            if (t1 - t2 < 4e-3f) {
                unsigned int slot = atomicAdd(&g_ambcnt, 1u);
                if (slot < AMB_CAP)
                    g_amb[slot] = (unsigned int)pos | ((unsigned int)m1 << 17)
                                                   | ((unsigned int)m2 << 24);
            }
        }
    }
}

// ---------------------------------------------------------------------------
// refine: R2 replay (sequential fp32 fmaf in (c,kh,kw) order, first-max tie).
// Reads from g_xt (bitwise-identical values, NHWC layout -> ~2.3KB L1-resident
// footprint per entry instead of 576 x 16KB-strided misses).
// ---------------------------------------------------------------------------
__global__ void __launch_bounds__(128) refine_kernel() {
    unsigned int total = g_ambcnt;
    if (total > AMB_CAP) total = AMB_CAP;
    unsigned int stride = gridDim.x * blockDim.x;
    for (unsigned int e = blockIdx.x * blockDim.x + threadIdx.x; e < total; e += stride) {
        unsigned int ent = g_amb[e];
        int pos = (int)(ent & 0x1FFFF);
        int ka  = (int)((ent >> 17) & 0x7F);
        int kb  = (int)((ent >> 24) & 0x7F);
        int bb = pos / (OH*OW);
        int r  = pos - bb*(OH*OW);
        int oh = r / OW;
        int ow = r - oh*OW;
        const float* xb = g_xt + ((((size_t)bb*H_ + oh)*W_ + ow) << 6);
        const float* wa = g_wnf + ka*576;
        const float* wb = g_wnf + kb*576;
        float sa = 0.f, sb2 = 0.f;
        #pragma unroll 1
        for (int c = 0; c < C_; c++) {
            const float* wac = wa + c*9;
            const float* wbc = wb + c*9;
            #pragma unroll
            for (int ii = 0; ii < 3; ii++)
                #pragma unroll
                for (int jj = 0; jj < 3; jj++) {
                    float xv = xb[(ii*W_ + jj)*64 + c];
                    sa  = fmaf(xv, wac[ii*3 + jj], sa);
                    sb2 = fmaf(xv, wbc[ii*3 + jj], sb2);
                }
        }
        int klo, khi; float dlo, dhi;
        if (ka < kb) { klo = ka; khi = kb; dlo = sa; dhi = sb2; }
        else         { klo = kb; khi = ka; dlo = sb2; dhi = sa; }
        g_winners[pos] = (dhi > dlo) ? khi : klo;
    }
}

// ---------------------------------------------------------------------------
__global__ void __launch_bounds__(256) bucket_kernel() {
    int pos = blockIdx.x * blockDim.x + threadIdx.x;
    if (pos >= NPOS) return;
    int k = g_winners[pos];
    int slot = atomicAdd(&g_kcnt[k], 1);
    g_klist[(size_t)k*NPOS + slot] = pos;
}

// ---------------------------------------------------------------------------
// hebb: bucketed, NHWC-coalesced.
// ---------------------------------------------------------------------------
__global__ void __launch_bounds__(256) hebb_kernel(float* __restrict__ upd) {
    const int k   = blockIdx.x;
    const int ch  = blockIdx.y;
    const int tid = threadIdx.x;
    const int n   = g_kcnt[k];
    const int lo  = (int)((long long)n * ch / 16);
    const int hi  = (int)((long long)n * (ch + 1) / 16);

    const int f0 = tid,       ij0 = f0 >> 6, c0 = f0 & 63;
    const int f1 = tid + 256, ij1 = f1 >> 6, c1 = f1 & 63;
    const int f2 = tid + 512, ij2 = f2 >> 6, c2 = f2 & 63;
    const int off0 = ((ij0/3)*W_ + (ij0%3))*64 + c0;
    const int off1 = ((ij1/3)*W_ + (ij1%3))*64 + c1;
    const int off2 = (f2 < 576) ? ((ij2/3)*W_ + (ij2%3))*64 + c2 : 0;
    float a0 = 0.f, a1 = 0.f, a2 = 0.f;

    const int* list = g_klist + (size_t)k*NPOS;
    #pragma unroll 1
    for (int t = lo; t < hi; t++) {
        int pos = list[t];
        int bb = pos / (OH*OW);
        int r  = pos - bb*(OH*OW);
        int oh = r / OW;
        int ow = r - oh*OW;
        const float* xb = g_xt + ((((size_t)bb*H_ + oh)*W_ + ow) << 6);
        a0 += xb[off0];
        a1 += xb[off1];
        if (f2 < 576) a2 += xb[off2];
    }
    const float s = 1.0f / (123008.0f + 1e-8f);
    if (lo < hi) {
        atomicAdd(&upd[k*576 + c0*9 + ij0], a0 * s);
        atomicAdd(&upd[k*576 + c1*9 + ij1], a1 * s);
        if (f2 < 576) atomicAdd(&upd[k*576 + c2*9 + ij2], a2 * s);
    }
}

// ---------------------------------------------------------------------------
extern "C" void kernel_launch(void* const* d_in, const int* in_sizes, int n_in,
                              void* d_out, int out_size) {
    const float* x    = (const float*)d_in[0];
    const float* w    = (const float*)d_in[1];
    const float* bias = (const float*)d_in[2];
    float* y   = (float*)d_out;
    float* upd = y + YSZ;

    cudaFuncSetAttribute(conv_mma_kernel,
                         cudaFuncAttributeMaxDynamicSharedMemorySize, SMEM_BYTES);

    prep_x_kernel<<<(int)(((size_t)B_*C_*H_*W_ + 255)/256), 256>>>(x);
    transpose_kernel<<<B_*H_, 256>>>(x);
    prep_w_kernel<<<9, 128>>>(w);
    zero_kernel<<<(UPDSZ + 255)/256, 256>>>(upd);
    conv_mma_kernel<<<dim3(OH/2, B_), 256, SMEM_BYTES>>>(bias, y);
    refine_kernel<<<128, 128>>>();
    bucket_kernel<<<(NPOS + 255)/256, 256>>>();
    hebb_kernel<<<dim3(K_, 16), 256>>>(upd);
}

// round 13
// speedup vs baseline: 1.0628x; 1.0628x over previous
#include <cuda_runtime.h>
#include <cuda_bf16.h>
#include <cstdint>
#include <math.h>

#define B_    32
#define C_    64
#define H_    64
#define W_    64
#define K_    128
#define OH    62
#define OW    62
#define NPOS  (B_*OH*OW)             // 123008
#define YSZ   ((size_t)B_*K_*OH*OW)  // 15745024
#define UPDSZ (K_*C_*9)              // 73728
#define AMB_CAP 32768

// ---------------------------------------------------------------------------
// device globals
// ---------------------------------------------------------------------------
__device__ __nv_bfloat16 g_xh[(size_t)B_*C_*H_*W_];
__device__ __nv_bfloat16 g_xl[(size_t)B_*C_*H_*W_];
__device__ float g_xt[(size_t)B_*H_*W_*C_];           // NHWC fp32 copy (exact values)
__device__ __nv_bfloat16 g_wpack[9 * 2*4*128*8*2];    // b-frag packed, 9 x 32KB
__device__ float g_wnf[K_*576];                       // normalized fp32 weights (R2-bit)
__device__ int g_winners[NPOS];
__device__ unsigned int g_ambcnt;
__device__ unsigned int g_amb[AMB_CAP];               // pos | k1<<17 | k2<<24
__device__ int g_kcnt[K_];
__device__ int g_klist[(size_t)K_*NPOS];

// ---------------------------------------------------------------------------
// helpers
// ---------------------------------------------------------------------------
__device__ __forceinline__ uint32_t smem_to_u32(const void* p) {
    uint32_t a;
    asm("{ .reg .u64 t; cvta.to.shared.u64 t, %1; cvt.u32.u64 %0, t; }" : "=r"(a) : "l"(p));
    return a;
}
__device__ __forceinline__ void ldmx4(uint32_t* r, uint32_t addr) {
    asm volatile("ldmatrix.sync.aligned.m8n8.x4.shared.b16 {%0,%1,%2,%3}, [%4];"
                 : "=r"(r[0]), "=r"(r[1]), "=r"(r[2]), "=r"(r[3]) : "r"(addr));
}
__device__ __forceinline__ void lds64(uint32_t* r, uint32_t addr) {
    asm volatile("ld.shared.v2.u32 {%0,%1}, [%2];" : "=r"(r[0]), "=r"(r[1]) : "r"(addr));
}
__device__ __forceinline__ void mma16816(float* c, const uint32_t* a, const uint32_t* b) {
    asm volatile("mma.sync.aligned.m16n8k16.row.col.f32.bf16.bf16.f32 "
                 "{%0,%1,%2,%3}, {%4,%5,%6,%7}, {%8,%9}, {%0,%1,%2,%3};"
                 : "+f"(c[0]), "+f"(c[1]), "+f"(c[2]), "+f"(c[3])
                 : "r"(a[0]), "r"(a[1]), "r"(a[2]), "r"(a[3]), "r"(b[0]), "r"(b[1]));
}

// ---------------------------------------------------------------------------
// prep_fused: ONE read of x -> writes g_xh, g_xl (NCHW bf16 split) and
// g_xt (NHWC fp32) via smem-tiled transpose. Block = (b,h) slab.
// ---------------------------------------------------------------------------
__global__ void __launch_bounds__(256) prep_fused_kernel(const float* __restrict__ x) {
    __shared__ float t[64][65];
    const int bh = blockIdx.x;
    const int b  = bh >> 6;
    const int h  = bh & 63;
    const int tid = threadIdx.x;
    for (int idx = tid; idx < 4096; idx += 256) {
        int c = idx >> 6, w = idx & 63;
        size_t gi = (((size_t)(b*64 + c))*64 + h)*64 + w;
        float v = x[gi];
        t[c][w] = v;
        __nv_bfloat16 hh = __float2bfloat16(v);
        __nv_bfloat16 ll = __float2bfloat16(v - __bfloat162float(hh));
        g_xh[gi] = hh;
        g_xl[gi] = ll;
    }
    __syncthreads();
    for (int idx = tid; idx < 4096; idx += 256) {
        int w = idx >> 6, c = idx & 63;
        g_xt[(((size_t)(b*64 + h))*64 + w)*64 + c] = t[c][w];
    }
}

// prep_w: R2-bit fp32 normalization + bf16 split + b-frag pack + fp32 copy.
__global__ void prep_w_kernel(const float* __restrict__ w) {
    int n  = threadIdx.x;
    int ij = blockIdx.x;
    float s = 0.f;
    for (int i = 0; i < 576; i++) { float v = w[n*576 + i]; s = fmaf(v, v, s); }
    float nm = sqrtf(s);
    if (nm == 0.f) nm = 1.f;
    float inv = 1.0f / nm;
    for (int c = 0; c < C_; c++) {
        float v = w[n*576 + c*9 + ij] * inv;
        g_wnf[n*576 + c*9 + ij] = v;
        __nv_bfloat16 h = __float2bfloat16(v);
        __nv_bfloat16 l = __float2bfloat16(v - __bfloat162float(h));
        int kc   = c >> 4;
        int cc   = c & 15;
        int widx = ((cc >> 1) & 3) * 2 + (cc >> 3);
        int half = cc & 1;
        size_t base = ((((size_t)ij*2 + 0)*4 + kc)*128 + n)*8 + widx;
        g_wpack[base*2 + half] = h;
        base = ((((size_t)ij*2 + 1)*4 + kc)*128 + n)*8 + widx;
        g_wpack[base*2 + half] = l;
    }
}

__global__ void zero_kernel(float* __restrict__ upd) {
    int i = blockIdx.x * blockDim.x + threadIdx.x;
    if (i < UPDSZ) upd[i] = 0.f;
    if (i < K_) g_kcnt[i] = 0;
    if (i == 0) g_ambcnt = 0;
}

// ---------------------------------------------------------------------------
// conv_mma: HMMA GEMM (R10-verified form: smem W staging, lds64 B frags).
// CTA = (b, 2 output rows) -> 128 pos x 128 k. Coalesced k-major y stores.
// ---------------------------------------------------------------------------
#define SOFF_BIAS 0
#define SOFF_TH   1024
#define SOFF_TL   33792
#define SOFF_W    66560
#define SOFF_D    1024
#define SMEM_BYTES 99328

__global__ void __launch_bounds__(256) conv_mma_kernel(
    const float* __restrict__ bias, float* __restrict__ y)
{
    extern __shared__ unsigned char smem[];
    const uint32_t sb = smem_to_u32(smem);
    const int tid = threadIdx.x;
    const int l   = tid & 31;
    const int wid = tid >> 5;
    const int wm  = wid >> 2;
    const int wn  = wid & 3;
    const int b   = blockIdx.y;
    const int oh0 = blockIdx.x * 2;

    if (tid < 128) ((float*)(smem + SOFF_BIAS))[tid] = bias[tid];

    for (int idx = tid; idx < C_*4*16; idx += 256) {
        int c    = idx >> 6;
        int row  = (idx >> 4) & 3;
        int col4 = (idx & 15) * 4;
        size_t gi = (((size_t)b*C_ + c)*H_ + (oh0 + row))*W_ + col4;
        const __nv_bfloat16* ph = g_xh + gi;
        const __nv_bfloat16* pl = g_xl + gi;
        #pragma unroll
        for (int q = 0; q < 4; q++) {
            int col = col4 + q;
            int rowIdx = row*64 + col;
            uint32_t off = (uint32_t)(rowIdx*128 + c*2) ^ (uint32_t)((rowIdx & 7) << 4);
            *(__nv_bfloat16*)(smem + SOFF_TH + off) = ph[q];
            *(__nv_bfloat16*)(smem + SOFF_TL + off) = pl[q];
        }
    }

    float acc[4][4][4] = {};
    const int lrow_lo = (l & 7) + ((l >> 3) & 1) * 8;
    const uint32_t khalf = (uint32_t)((l >> 4) * 16);

    #pragma unroll 1
    for (int s = 0; s < 9; s++) {
        const int i = s / 3, j = s - 3*(s/3);
        __syncthreads();
        {
            const uint4* src = (const uint4*)((const __nv_bfloat16*)g_wpack + (size_t)s*16384);
            uint4* dst = (uint4*)(smem + SOFF_W);
            #pragma unroll
            for (int t = 0; t < 8; t++) dst[tid + t*256] = src[tid + t*256];
        }
        __syncthreads();

        uint32_t abase[4], asw[4];
        #pragma unroll
        for (int mt = 0; mt < 4; mt++) {
            int m  = wm*64 + mt*16 + lrow_lo;
            int nr = m >> 6, nc = m & 63;
            int pc = nc + j; if (pc > 63) pc = 63;
            int rowIdx = (nr + i)*64 + pc;
            abase[mt] = sb + SOFF_TH + (uint32_t)(rowIdx*128);
            asw[mt]   = (uint32_t)((rowIdx & 7) << 4);
        }

        const uint32_t swb = sb + SOFF_W;
        #pragma unroll 1
        for (int kc = 0; kc < 4; kc++) {
            const uint32_t koff = (uint32_t)kc * 32;
            uint32_t ah[4][4], bh[4][2];
            #pragma unroll
            for (int mt = 0; mt < 4; mt++)
                ldmx4(ah[mt], abase[mt] + ((khalf + koff) ^ asw[mt]));
            #pragma unroll
            for (int nt = 0; nt < 4; nt++) {
                int n = wn*32 + nt*8 + (l >> 2);
                lds64(bh[nt], swb + (uint32_t)((((0*4 + kc)*128 + n)*8 + (l & 3)*2) * 4));
            }
            #pragma unroll
            for (int mt = 0; mt < 4; mt++)
                #pragma unroll
                for (int nt = 0; nt < 4; nt++)
                    mma16816(acc[mt][nt], ah[mt], bh[nt]);
            {
                uint32_t al[4][4];
                #pragma unroll
                for (int mt = 0; mt < 4; mt++)
                    ldmx4(al[mt], abase[mt] + 32768 + ((khalf + koff) ^ asw[mt]));
                #pragma unroll
                for (int mt = 0; mt < 4; mt++)
                    #pragma unroll
                    for (int nt = 0; nt < 4; nt++)
                        mma16816(acc[mt][nt], al[mt], bh[nt]);
            }
            {
                uint32_t bl[4][2];
                #pragma unroll
                for (int nt = 0; nt < 4; nt++) {
                    int n = wn*32 + nt*8 + (l >> 2);
                    lds64(bl[nt], swb + (uint32_t)((((1*4 + kc)*128 + n)*8 + (l & 3)*2) * 4));
                }
                #pragma unroll
                for (int mt = 0; mt < 4; mt++)
                    #pragma unroll
                    for (int nt = 0; nt < 4; nt++)
                        mma16816(acc[mt][nt], ah[mt], bl[nt]);
            }
        }
    }

    // ---- epilogue: frags -> smem D[128][130] ----
    __syncthreads();
    float* D = (float*)(smem + SOFF_D);
    {
        const int r  = l >> 2;
        const int cq = (l & 3) * 2;
        #pragma unroll
        for (int mt = 0; mt < 4; mt++)
            #pragma unroll
            for (int nt = 0; nt < 4; nt++) {
                int pos = wm*64 + mt*16 + r;
                int k   = wn*32 + nt*8 + cq;
                *(float2*)&D[pos*130 + k]       = make_float2(acc[mt][nt][0], acc[mt][nt][1]);
                *(float2*)&D[(pos + 8)*130 + k] = make_float2(acc[mt][nt][2], acc[mt][nt][3]);
            }
    }
    __syncthreads();

    const float* bs = (const float*)(smem + SOFF_BIAS);

    // ---- phase 1: per-thread top-2 over 64 k (pos = tid>>1, half by tid&1) ----
    const int p2   = tid >> 1;
    const int kh2  = (tid & 1) * 64;
    const int nrow = p2 >> 6, ncol = p2 & 63;
    const int oh = oh0 + nrow, ow = ncol;
    const bool valid = (ncol < OW);
    float v1 = -INFINITY, v2 = -INFINITY;
    int   k1 = 0, k2 = 0;
    #pragma unroll 4
    for (int k = kh2; k < kh2 + 64; k += 2) {
        float2 d = *(float2*)&D[p2*130 + k];
        float a0 = d.x + bs[k];
        float a1 = d.y + bs[k+1];
        if (a0 > v1) { v2 = v1; k2 = k1; v1 = a0; k1 = k; }
        else if (a0 > v2) { v2 = a0; k2 = k; }
        if (a1 > v1) { v2 = v1; k2 = k1; v1 = a1; k1 = k + 1; }
        else if (a1 > v2) { v2 = a1; k2 = k + 1; }
    }

    // ---- phase 2: coalesced k-major y stores (warp owns 16 k's) ----
    #pragma unroll 1
    for (int it = 0; it < 16; it++) {
        int k = wid*16 + it;
        float bv = bs[k];
        #pragma unroll
        for (int r = 0; r < 2; r++) {
            float* yrow = y + (((size_t)b*K_ + k)*OH + (oh0 + r))*OW;
            float u0 = D[(r*64 + l)*130 + k] + bv;
            yrow[l] = u0;                               // cols 0..31
            if (l < 30) {
                float u1 = D[(r*64 + 32 + l)*130 + k] + bv;
                yrow[32 + l] = u1;                      // cols 32..61
            }
        }
    }
    __syncthreads();

    // ---- phase 3: merge halves, write winners, flag near-ties ----
    {
        float* rv = (float*)(smem + SOFF_D);           // D dead now
        int*   rk = (int*)(smem + SOFF_D + 4096);
        rv[tid*2] = v1; rv[tid*2+1] = v2;
        rk[tid*2] = k1; rk[tid*2+1] = k2;
        __syncthreads();
        if ((tid & 1) == 0 && valid) {
            float w1 = rv[(tid+1)*2], w2 = rv[(tid+1)*2+1];
            int   j1 = rk[(tid+1)*2], j2 = rk[(tid+1)*2+1];
            float t1, t2; int m1, m2;
            if (w1 > v1) { t1 = w1; m1 = j1; t2 = (v1 > w2) ? v1 : w2; m2 = (v1 > w2) ? k1 : j2; }
            else         { t1 = v1; m1 = k1; t2 = (w1 > v2) ? w1 : v2; m2 = (w1 > v2) ? j1 : k2; }
            int pos = (b*OH + oh)*OW + ow;
            g_winners[pos] = m1;
            if (t1 - t2 < 4e-3f) {
                unsigned int slot = atomicAdd(&g_ambcnt, 1u);
                if (slot < AMB_CAP)
                    g_amb[slot] = (unsigned int)pos | ((unsigned int)m1 << 17)
                                                   | ((unsigned int)m2 << 24);
            }
        }
    }
}

// ---------------------------------------------------------------------------
// refine: R2 replay (sequential fp32 fmaf in (c,kh,kw) order, first-max tie),
// reading bitwise-identical x values from the NHWC copy.
// ---------------------------------------------------------------------------
__global__ void __launch_bounds__(128) refine_kernel() {
    unsigned int total = g_ambcnt;
    if (total > AMB_CAP) total = AMB_CAP;
    unsigned int stride = gridDim.x * blockDim.x;
    for (unsigned int e = blockIdx.x * blockDim.x + threadIdx.x; e < total; e += stride) {
        unsigned int ent = g_amb[e];
        int pos = (int)(ent & 0x1FFFF);
        int ka  = (int)((ent >> 17) & 0x7F);
        int kb  = (int)((ent >> 24) & 0x7F);
        int bb = pos / (OH*OW);
        int r  = pos - bb*(OH*OW);
        int oh = r / OW;
        int ow = r - oh*OW;
        const float* xb = g_xt + ((((size_t)bb*H_ + oh)*W_ + ow) << 6);
        const float* wa = g_wnf + ka*576;
        const float* wb = g_wnf + kb*576;
        float sa = 0.f, sb2 = 0.f;
        #pragma unroll 1
        for (int c = 0; c < C_; c++) {
            const float* wac = wa + c*9;
            const float* wbc = wb + c*9;
            #pragma unroll
            for (int ii = 0; ii < 3; ii++)
                #pragma unroll
                for (int jj = 0; jj < 3; jj++) {
                    float xv = xb[(ii*W_ + jj)*64 + c];
                    sa  = fmaf(xv, wac[ii*3 + jj], sa);
                    sb2 = fmaf(xv, wbc[ii*3 + jj], sb2);
                }
        }
        int klo, khi; float dlo, dhi;
        if (ka < kb) { klo = ka; khi = kb; dlo = sa; dhi = sb2; }
        else         { klo = kb; khi = ka; dlo = sb2; dhi = sa; }
        g_winners[pos] = (dhi > dlo) ? khi : klo;
    }
}

// ---------------------------------------------------------------------------
__global__ void __launch_bounds__(256) bucket_kernel() {
    int pos = blockIdx.x * blockDim.x + threadIdx.x;
    if (pos >= NPOS) return;
    int k = g_winners[pos];
    int slot = atomicAdd(&g_kcnt[k], 1);
    g_klist[(size_t)k*NPOS + slot] = pos;
}

// ---------------------------------------------------------------------------
// hebb: bucketed, NHWC-coalesced.
// ---------------------------------------------------------------------------
__global__ void __launch_bounds__(256) hebb_kernel(float* __restrict__ upd) {
    const int k   = blockIdx.x;
    const int ch  = blockIdx.y;
    const int tid = threadIdx.x;
    const int n   = g_kcnt[k];
    const int lo  = (int)((long long)n * ch / 16);
    const int hi  = (int)((long long)n * (ch + 1) / 16);

    const int f0 = tid,       ij0 = f0 >> 6, c0 = f0 & 63;
    const int f1 = tid + 256, ij1 = f1 >> 6, c1 = f1 & 63;
    const int f2 = tid + 512, ij2 = f2 >> 6, c2 = f2 & 63;
    const int off0 = ((ij0/3)*W_ + (ij0%3))*64 + c0;
    const int off1 = ((ij1/3)*W_ + (ij1%3))*64 + c1;
    const int off2 = (f2 < 576) ? ((ij2/3)*W_ + (ij2%3))*64 + c2 : 0;
    float a0 = 0.f, a1 = 0.f, a2 = 0.f;

    const int* list = g_klist + (size_t)k*NPOS;
    #pragma unroll 1
    for (int t = lo; t < hi; t++) {
        int pos = list[t];
        int bb = pos / (OH*OW);
        int r  = pos - bb*(OH*OW);
        int oh = r / OW;
        int ow = r - oh*OW;
        const float* xb = g_xt + ((((size_t)bb*H_ + oh)*W_ + ow) << 6);
        a0 += xb[off0];
        a1 += xb[off1];
        if (f2 < 576) a2 += xb[off2];
    }
    const float s = 1.0f / (123008.0f + 1e-8f);
    if (lo < hi) {
        atomicAdd(&upd[k*576 + c0*9 + ij0], a0 * s);
        atomicAdd(&upd[k*576 + c1*9 + ij1], a1 * s);
        if (f2 < 576) atomicAdd(&upd[k*576 + c2*9 + ij2], a2 * s);
    }
}

// ---------------------------------------------------------------------------
extern "C" void kernel_launch(void* const* d_in, const int* in_sizes, int n_in,
                              void* d_out, int out_size) {
    const float* x    = (const float*)d_in[0];
    const float* w    = (const float*)d_in[1];
    const float* bias = (const float*)d_in[2];
    float* y   = (float*)d_out;
    float* upd = y + YSZ;

    cudaFuncSetAttribute(conv_mma_kernel,
                         cudaFuncAttributeMaxDynamicSharedMemorySize, SMEM_BYTES);

    prep_fused_kernel<<<B_*H_, 256>>>(x);
    prep_w_kernel<<<9, 128>>>(w);
    zero_kernel<<<(UPDSZ + 255)/256, 256>>>(upd);
    conv_mma_kernel<<<dim3(OH/2, B_), 256, SMEM_BYTES>>>(bias, y);
    refine_kernel<<<128, 128>>>();
    bucket_kernel<<<(NPOS + 255)/256, 256>>>();
    hebb_kernel<<<dim3(K_, 16), 256>>>(upd);
}